// round 4
// baseline (speedup 1.0000x reference)
#include <cuda_runtime.h>

#define DIM 1024
#define NPAIRS 512
#define ROWS_PER_BLK 8
#define THREADS 256        // 8 warps, one row per warp

// Composite complex butterfly coefficients, one per adjacent pair.
__device__ float2 g_coef[NPAIRS];

// W_j = prod_{l=1..9} (a_l - i b_l); level-l params at offset 4096 - 2^(12-l),
// block index for pair j is j >> (l-1). (l=0 params unused: bs<2.)
__global__ void coef_kernel(const float* __restrict__ params) {
    int j = blockIdx.x * blockDim.x + threadIdx.x;
    if (j >= NPAIRS) return;
    float Wr = 1.0f, Wi = 0.0f;
#pragma unroll
    for (int l = 1; l <= 9; ++l) {
        int off = 4096 - (1 << (12 - l));
        int blk = j >> (l - 1);
        float a = params[off + 2 * blk];
        float b = params[off + 2 * blk + 1];
        float nr = Wr * a + Wi * b;     // (Wr + i Wi) *= (a - i b)
        float ni = Wi * a - Wr * b;
        Wr = nr; Wi = ni;
    }
    g_coef[j] = make_float2(Wr, Wi);
}

// Warp-per-row: no shared memory, no block barriers. Each lane holds 8 float4
// of data and 8 float4 of coefficients (all loads front-batched), reduces two
// sums in one shuffle tree, then scales & stores.
__global__ __launch_bounds__(THREADS) void hyper_butterfly_kernel(
    const float4* __restrict__ x, float4* __restrict__ out)
{
    const int lane = threadIdx.x & 31;
    const int wid  = threadIdx.x >> 5;

    const size_t row  = (size_t)blockIdx.x * ROWS_PER_BLK + wid;
    const size_t base = row * (DIM / 4);
    const float4* W4  = (const float4*)g_coef;

    // ---- front-batched loads: 8 DRAM + 8 L2 ----
    float4 v[8], w[8];
#pragma unroll
    for (int i = 0; i < 8; ++i) v[i] = __ldg(x + base + lane + 32 * i);
#pragma unroll
    for (int i = 0; i < 8; ++i) w[i] = __ldg(W4 + lane + 32 * i);

    // ---- partial sums: ||x||^2 and ||W z||^2 = sum |W_j|^2 |z_j|^2 ----
    float ss = 0.0f, ss2 = 0.0f;
#pragma unroll
    for (int i = 0; i < 8; ++i) {
        float4 vv = v[i], ww = w[i];
        float p0 = vv.x * vv.x + vv.y * vv.y;   // |z_{2j}|^2
        float p1 = vv.z * vv.z + vv.w * vv.w;   // |z_{2j+1}|^2
        float q0 = ww.x * ww.x + ww.y * ww.y;   // |W_{2j}|^2
        float q1 = ww.z * ww.z + ww.w * ww.w;   // |W_{2j+1}|^2
        ss  += p0 + p1;
        ss2 += q0 * p0 + q1 * p1;
    }

    // ---- single warp reduction, two interleaved trees ----
#pragma unroll
    for (int o = 16; o; o >>= 1) {
        ss  += __shfl_xor_sync(0xFFFFFFFFu, ss,  o);
        ss2 += __shfl_xor_sync(0xFFFFFFFFu, ss2, o);
    }

    float n  = sqrtf(ss);
    float s1 = (n > 0.0f) ? (atanhf(n) / n) : 1.0f;      // log_map(0,x) scale
    float vn = fmaxf(s1 * sqrtf(ss2), 1e-8f);            // ||u||
    float s  = s1 * (tanhf(vn) / vn);                    // total scale

    // ---- rotate, scale, store (v and w still live) ----
#pragma unroll
    for (int i = 0; i < 8; ++i) {
        float4 vv = v[i], ww = w[i];
        float4 o4;
        o4.x = s * (ww.x * vv.x - ww.y * vv.y);
        o4.y = s * (ww.y * vv.x + ww.x * vv.y);
        o4.z = s * (ww.z * vv.z - ww.w * vv.w);
        o4.w = s * (ww.w * vv.z + ww.z * vv.w);
        out[base + lane + 32 * i] = o4;
    }
}

extern "C" void kernel_launch(void* const* d_in, const int* in_sizes, int n_in,
                              void* d_out, int out_size) {
    const float* xp = (const float*)d_in[0];
    const float* pp = (const float*)d_in[1];
    long long n0 = in_sizes[0], n1 = in_sizes[1];
    if (n0 < n1) { const float* tmp = xp; xp = pp; pp = tmp; long long ts = n0; n0 = n1; n1 = ts; }
    int rows = (int)(n0 / DIM);

    coef_kernel<<<1, NPAIRS>>>(pp);
    hyper_butterfly_kernel<<<rows / ROWS_PER_BLK, THREADS>>>(
        (const float4*)xp, (float4*)d_out);
}

// round 5
// speedup vs baseline: 1.0344x; 1.0344x over previous
#include <cuda_runtime.h>

#define DIM 1024
#define NPAIRS 512
#define ROWS_PER_BLK 8
#define THREADS 256        // 8 warps, one row per warp

// Composite complex butterfly coefficients, one per adjacent pair.
__device__ float2 g_coef[NPAIRS];

// W_j = prod_{l=1..9} (a_l - i b_l); level-l params at offset 4096 - 2^(12-l),
// block index for pair j is j >> (l-1). (l=0 params unused: bs<2.)
__global__ void coef_kernel(const float* __restrict__ params) {
    int j = blockIdx.x * blockDim.x + threadIdx.x;
    if (j >= NPAIRS) return;
    float Wr = 1.0f, Wi = 0.0f;
#pragma unroll
    for (int l = 1; l <= 9; ++l) {
        int off = 4096 - (1 << (12 - l));
        int blk = j >> (l - 1);
        float a = params[off + 2 * blk];
        float b = params[off + 2 * blk + 1];
        float nr = Wr * a + Wi * b;     // (Wr + i Wi) *= (a - i b)
        float ni = Wi * a - Wr * b;
        Wr = nr; Wi = ni;
    }
    g_coef[j] = make_float2(Wr, Wi);
}

// Warp-per-row. Coefficients staged in smem once per block (kills the 128 MB
// of redundant L2 coefficient traffic that was saturating the LTS crossbar).
// Input read with __ldcs / output written with __stcs (streaming, no reuse).
__global__ __launch_bounds__(THREADS) void hyper_butterfly_kernel(
    const float4* __restrict__ x, float4* __restrict__ out)
{
    __shared__ float4 wsh[NPAIRS / 2];   // 256 float4 = 4 KB

    const int tid  = threadIdx.x;
    const int lane = tid & 31;
    const int wid  = tid >> 5;

    // ---- stage coefficient table: one float4 per thread ----
    wsh[tid] = ((const float4*)g_coef)[tid];

    const size_t base = ((size_t)blockIdx.x * ROWS_PER_BLK + wid) * (DIM / 4);

    // ---- front-batched row loads (MLP=8, streaming) ----
    float4 v[8];
#pragma unroll
    for (int i = 0; i < 8; ++i) v[i] = __ldcs(x + base + lane + 32 * i);

    __syncthreads();

    // ---- partial sums: ||x||^2 and ||W z||^2 = sum |W_j|^2 |z_j|^2 ----
    float ss = 0.0f, ss2 = 0.0f;
#pragma unroll
    for (int i = 0; i < 8; ++i) {
        float4 vv = v[i];
        float4 ww = wsh[lane + 32 * i];      // conflict-free LDS.128
        float p0 = vv.x * vv.x + vv.y * vv.y;
        float p1 = vv.z * vv.z + vv.w * vv.w;
        float q0 = ww.x * ww.x + ww.y * ww.y;
        float q1 = ww.z * ww.z + ww.w * ww.w;
        ss  += p0 + p1;
        ss2 += q0 * p0 + q1 * p1;
    }

    // ---- single warp reduction, two interleaved trees ----
#pragma unroll
    for (int o = 16; o; o >>= 1) {
        ss  += __shfl_xor_sync(0xFFFFFFFFu, ss,  o);
        ss2 += __shfl_xor_sync(0xFFFFFFFFu, ss2, o);
    }

    float n  = sqrtf(ss);
    float s1 = (n > 0.0f) ? (atanhf(n) / n) : 1.0f;      // log_map(0,x) scale
    float vn = fmaxf(s1 * sqrtf(ss2), 1e-8f);            // ||u||
    float s  = s1 * (tanhf(vn) / vn);                    // total scale

    // ---- rotate, scale, streaming store ----
#pragma unroll
    for (int i = 0; i < 8; ++i) {
        float4 vv = v[i];
        float4 ww = wsh[lane + 32 * i];
        float4 o4;
        o4.x = s * (ww.x * vv.x - ww.y * vv.y);
        o4.y = s * (ww.y * vv.x + ww.x * vv.y);
        o4.z = s * (ww.z * vv.z - ww.w * vv.w);
        o4.w = s * (ww.w * vv.z + ww.z * vv.w);
        __stcs(out + base + lane + 32 * i, o4);
    }
}

extern "C" void kernel_launch(void* const* d_in, const int* in_sizes, int n_in,
                              void* d_out, int out_size) {
    const float* xp = (const float*)d_in[0];
    const float* pp = (const float*)d_in[1];
    long long n0 = in_sizes[0], n1 = in_sizes[1];
    if (n0 < n1) { const float* tmp = xp; xp = pp; pp = tmp; long long ts = n0; n0 = n1; n1 = ts; }
    int rows = (int)(n0 / DIM);

    coef_kernel<<<1, NPAIRS>>>(pp);
    hyper_butterfly_kernel<<<rows / ROWS_PER_BLK, THREADS>>>(
        (const float4*)xp, (float4*)d_out);
}